// round 1
// baseline (speedup 1.0000x reference)
#include <cuda_runtime.h>
#include <math.h>

// Problem constants
#define BB  2
#define TT  4096
#define CC  512
#define HH  8
#define DD  64
#define FF2 2048
#define NR  (BB*TT)          // 8192 rows

// ---------------------------------------------------------------------------
// Scratch (device-global; no runtime allocation allowed)
// layout (floats):
//   h   : [NR*CC]   ln1 output
//   q   : [NR*CC]
//   k   : [NR*CC]
//   v   : [NR*CC]
//   attn: [NR*CC]
//   x1  : [NR*CC]   residual after attention
//   h2  : [NR*CC]   ln2 output
//   ff  : [NR*FF2]  relu(h2@W1+b1)
// ---------------------------------------------------------------------------
__device__ float g_scratch[(size_t)NR*CC*7 + (size_t)NR*FF2];

// ---------------------------------------------------------------------------
// LayerNorm: one block per row, 128 threads, 4 elems/thread
// ---------------------------------------------------------------------------
__global__ void ln_kernel(const float* __restrict__ x, const float* __restrict__ g,
                          const float* __restrict__ b, float* __restrict__ y) {
    __shared__ float sbuf[4];
    int row = blockIdx.x;
    const float* xr = x + (size_t)row * CC;
    int t = threadIdx.x;
    float v[4];
    float s = 0.f;
#pragma unroll
    for (int i = 0; i < 4; i++) { v[i] = xr[t + i * 128]; s += v[i]; }
#pragma unroll
    for (int o = 16; o; o >>= 1) s += __shfl_xor_sync(0xffffffffu, s, o);
    if ((t & 31) == 0) sbuf[t >> 5] = s;
    __syncthreads();
    float mu = (sbuf[0] + sbuf[1] + sbuf[2] + sbuf[3]) * (1.f / CC);
    __syncthreads();
    float ss = 0.f;
#pragma unroll
    for (int i = 0; i < 4; i++) { float d = v[i] - mu; ss += d * d; }
#pragma unroll
    for (int o = 16; o; o >>= 1) ss += __shfl_xor_sync(0xffffffffu, ss, o);
    if ((t & 31) == 0) sbuf[t >> 5] = ss;
    __syncthreads();
    float inv = rsqrtf((sbuf[0] + sbuf[1] + sbuf[2] + sbuf[3]) * (1.f / CC) + 1e-5f);
    float* yr = y + (size_t)row * CC;
#pragma unroll
    for (int i = 0; i < 4; i++) {
        int c = t + i * 128;
        yr[c] = (v[i] - mu) * inv * g[c] + b[c];
    }
}

// ---------------------------------------------------------------------------
// SGEMM: C = A[M,K] @ B[K,N] with epilogue
//   EPI=0: none
//   EPI=1: relu(acc + bias[n])
//   EPI=2: acc + bias[n] + res[m*N+n]
// 128x128 block tile, BK=8, 8x8 per thread, 256 threads.
// Requires M%128==0, N%128==0, K%8==0 (true for all our shapes).
// ---------------------------------------------------------------------------
template <int EPI>
__global__ void __launch_bounds__(256) sgemm_kernel(
    const float* __restrict__ A, const float* __restrict__ B,
    float* __restrict__ Cout, const float* __restrict__ bias,
    const float* __restrict__ res, int M, int N, int K) {
    const int BM = 128, BN = 128, BK = 8;
    __shared__ float As[BK][BM];
    __shared__ float Bs[BK][BN];

    int tid = threadIdx.x;
    int tx = tid & 15;        // 0..15  -> 8 cols each
    int ty = tid >> 4;        // 0..15  -> 8 rows each

    int aRow = tid >> 1;          // 0..127
    int aCol = (tid & 1) * 4;     // 0 or 4
    int bRow = tid >> 5;          // 0..7
    int bCol = (tid & 31) * 4;    // 0..124

    const float* Ab = A + (size_t)blockIdx.y * BM * K;
    const float* Bb = B + (size_t)blockIdx.x * BN;

    float acc[8][8];
#pragma unroll
    for (int i = 0; i < 8; i++)
#pragma unroll
        for (int j = 0; j < 8; j++) acc[i][j] = 0.f;

    for (int k0 = 0; k0 < K; k0 += BK) {
        float4 a4 = *(const float4*)(Ab + (size_t)aRow * K + k0 + aCol);
        As[aCol + 0][aRow] = a4.x;
        As[aCol + 1][aRow] = a4.y;
        As[aCol + 2][aRow] = a4.z;
        As[aCol + 3][aRow] = a4.w;
        float4 b4 = *(const float4*)(Bb + (size_t)(k0 + bRow) * N + bCol);
        *(float4*)&Bs[bRow][bCol] = b4;
        __syncthreads();
#pragma unroll
        for (int kk = 0; kk < BK; kk++) {
            float ar[8], br[8];
#pragma unroll
            for (int i = 0; i < 8; i++) ar[i] = As[kk][ty * 8 + i];
#pragma unroll
            for (int j = 0; j < 8; j++) br[j] = Bs[kk][tx * 8 + j];
#pragma unroll
            for (int i = 0; i < 8; i++)
#pragma unroll
                for (int j = 0; j < 8; j++) acc[i][j] += ar[i] * br[j];
        }
        __syncthreads();
    }

    int rowBase = blockIdx.y * BM + ty * 8;
    int colBase = blockIdx.x * BN + tx * 8;
#pragma unroll
    for (int i = 0; i < 8; i++) {
        size_t roff = (size_t)(rowBase + i) * N + colBase;
#pragma unroll
        for (int j = 0; j < 8; j++) {
            float val = acc[i][j];
            if (EPI == 1) val = fmaxf(val + bias[colBase + j], 0.f);
            if (EPI == 2) val = val + bias[colBase + j] + res[roff + j];
            Cout[roff + j] = val;
        }
    }
}

// ---------------------------------------------------------------------------
// Flash attention (causal), fp32.
// grid = (T/64, H, B), block = 128 threads.
// Q tile 64 rows x 64 dim, KV tiles 64x64, online softmax, P via smem.
// Score scale = C^-0.5 (folded into Q at load).
// q/k/v/o layout: [(b*T + t)*C + h*64 + d]
// ---------------------------------------------------------------------------
#define FSW 68   // padded smem row width
#define FLASH_SMEM (4 * 64 * FSW * 4)

__global__ void __launch_bounds__(128) flash_kernel(
    const float* __restrict__ q, const float* __restrict__ k,
    const float* __restrict__ v, float* __restrict__ o) {
    extern __shared__ float sm[];
    float* Qs = sm;
    float* Ks = Qs + 64 * FSW;
    float* Vs = Ks + 64 * FSW;
    float* Ps = Vs + 64 * FSW;

    int t = threadIdx.x;
    int qb = blockIdx.x;
    int hh = blockIdx.y;
    int bb = blockIdx.z;
    size_t hbase = ((size_t)bb * TT) * CC + (size_t)hh * DD;
    int qbase = qb * 64;
    const float scale = 0.04419417382415922f;  // 512^-0.5

    // load Q tile (scaled)
#pragma unroll
    for (int i = 0; i < 8; i++) {
        int idx = t + i * 128;
        int row = idx >> 4, c4 = (idx & 15) * 4;
        float4 val = *(const float4*)(q + hbase + (size_t)(qbase + row) * CC + c4);
        val.x *= scale; val.y *= scale; val.z *= scale; val.w *= scale;
        *(float4*)&Qs[row * FSW + c4] = val;
    }

    int ty = t >> 3;  // 0..15 -> 4 query rows each
    int tx = t & 7;   // 0..7  -> 8 cols each
    float m[4], l[4], acc[4][8];
#pragma unroll
    for (int i = 0; i < 4; i++) {
        m[i] = -1e30f; l[i] = 0.f;
#pragma unroll
        for (int j = 0; j < 8; j++) acc[i][j] = 0.f;
    }

    for (int kb = 0; kb <= qb; kb++) {
        int kbase = kb * 64;
        __syncthreads();  // protect Ks/Vs/Ps reuse
#pragma unroll
        for (int i = 0; i < 8; i++) {
            int idx = t + i * 128;
            int row = idx >> 4, c4 = (idx & 15) * 4;
            *(float4*)&Ks[row * FSW + c4] =
                *(const float4*)(k + hbase + (size_t)(kbase + row) * CC + c4);
            *(float4*)&Vs[row * FSW + c4] =
                *(const float4*)(v + hbase + (size_t)(kbase + row) * CC + c4);
        }
        __syncthreads();

        // S = Qs @ Ks^T  (4x8 per thread)
        float s[4][8];
#pragma unroll
        for (int i = 0; i < 4; i++)
#pragma unroll
            for (int j = 0; j < 8; j++) s[i][j] = 0.f;
#pragma unroll 8
        for (int kk = 0; kk < 64; kk++) {
            float qr[4], kr[8];
#pragma unroll
            for (int i = 0; i < 4; i++) qr[i] = Qs[(ty * 4 + i) * FSW + kk];
#pragma unroll
            for (int j = 0; j < 8; j++) kr[j] = Ks[(tx * 8 + j) * FSW + kk];
#pragma unroll
            for (int i = 0; i < 4; i++)
#pragma unroll
                for (int j = 0; j < 8; j++) s[i][j] += qr[i] * kr[j];
        }

        if (kb == qb) {  // diagonal tile: causal mask
#pragma unroll
            for (int i = 0; i < 4; i++)
#pragma unroll
                for (int j = 0; j < 8; j++)
                    if (tx * 8 + j > ty * 4 + i) s[i][j] = -1e30f;
        }

        // online softmax update
#pragma unroll
        for (int i = 0; i < 4; i++) {
            float mt = s[i][0];
#pragma unroll
            for (int j = 1; j < 8; j++) mt = fmaxf(mt, s[i][j]);
#pragma unroll
            for (int off = 1; off < 8; off <<= 1)
                mt = fmaxf(mt, __shfl_xor_sync(0xffffffffu, mt, off));
            float mnew = fmaxf(m[i], mt);
            float corr = __expf(m[i] - mnew);
            float r = 0.f;
#pragma unroll
            for (int j = 0; j < 8; j++) {
                float p = __expf(s[i][j] - mnew);
                s[i][j] = p;
                r += p;
            }
#pragma unroll
            for (int off = 1; off < 8; off <<= 1)
                r += __shfl_xor_sync(0xffffffffu, r, off);
            l[i] = l[i] * corr + r;
            m[i] = mnew;
#pragma unroll
            for (int j = 0; j < 8; j++) acc[i][j] *= corr;
        }

        // stage P in smem for PV gemm
#pragma unroll
        for (int i = 0; i < 4; i++)
#pragma unroll
            for (int j = 0; j < 8; j++)
                Ps[(ty * 4 + i) * FSW + tx * 8 + j] = s[i][j];
        __syncthreads();

        // O += P @ V
#pragma unroll 8
        for (int c = 0; c < 64; c++) {
            float pr[4], vr[8];
#pragma unroll
            for (int i = 0; i < 4; i++) pr[i] = Ps[(ty * 4 + i) * FSW + c];
#pragma unroll
            for (int j = 0; j < 8; j++) vr[j] = Vs[c * FSW + tx * 8 + j];
#pragma unroll
            for (int i = 0; i < 4; i++)
#pragma unroll
                for (int j = 0; j < 8; j++) acc[i][j] += pr[i] * vr[j];
        }
    }

    // epilogue: normalize and write
#pragma unroll
    for (int i = 0; i < 4; i++) {
        float inv = 1.f / l[i];
        size_t off = hbase + (size_t)(qbase + ty * 4 + i) * CC + tx * 8;
        float4 o0 = make_float4(acc[i][0] * inv, acc[i][1] * inv,
                                acc[i][2] * inv, acc[i][3] * inv);
        float4 o1 = make_float4(acc[i][4] * inv, acc[i][5] * inv,
                                acc[i][6] * inv, acc[i][7] * inv);
        *(float4*)(o + off) = o0;
        *(float4*)(o + off + 4) = o1;
    }
}

// ---------------------------------------------------------------------------
// Launch
// ---------------------------------------------------------------------------
extern "C" void kernel_launch(void* const* d_in, const int* in_sizes, int n_in,
                              void* d_out, int out_size) {
    const float* x   = (const float*)d_in[0];
    const float* Wq  = (const float*)d_in[1];
    const float* Wk  = (const float*)d_in[2];
    const float* Wv  = (const float*)d_in[3];
    const float* Wo  = (const float*)d_in[4];
    const float* bo  = (const float*)d_in[5];
    const float* W1  = (const float*)d_in[6];
    const float* b1  = (const float*)d_in[7];
    const float* W2  = (const float*)d_in[8];
    const float* b2  = (const float*)d_in[9];
    const float* g1  = (const float*)d_in[10];
    const float* be1 = (const float*)d_in[11];
    const float* g2  = (const float*)d_in[12];
    const float* be2 = (const float*)d_in[13];
    float* out = (float*)d_out;

    float* base = nullptr;
    cudaGetSymbolAddress((void**)&base, g_scratch);
    const size_t SZ = (size_t)NR * CC;
    float* h    = base;
    float* q    = base + SZ * 1;
    float* k    = base + SZ * 2;
    float* v    = base + SZ * 3;
    float* attn = base + SZ * 4;
    float* x1   = base + SZ * 5;
    float* h2   = base + SZ * 6;
    float* ff   = base + SZ * 7;

    cudaFuncSetAttribute(flash_kernel,
                         cudaFuncAttributeMaxDynamicSharedMemorySize, FLASH_SMEM);

    // ln1
    ln_kernel<<<NR, 128>>>(x, g1, be1, h);

    // q,k,v = h @ W{q,k,v}
    dim3 g512(CC / 128, NR / 128);
    sgemm_kernel<0><<<g512, 256>>>(h, Wq, q, nullptr, nullptr, NR, CC, CC);
    sgemm_kernel<0><<<g512, 256>>>(h, Wk, k, nullptr, nullptr, NR, CC, CC);
    sgemm_kernel<0><<<g512, 256>>>(h, Wv, v, nullptr, nullptr, NR, CC, CC);

    // attention
    flash_kernel<<<dim3(TT / 64, HH, BB), 128, FLASH_SMEM>>>(q, k, v, attn);

    // x1 = x + attn @ Wo + bo
    sgemm_kernel<2><<<g512, 256>>>(attn, Wo, x1, bo, x, NR, CC, CC);

    // ln2
    ln_kernel<<<NR, 128>>>(x1, g2, be2, h2);

    // ff = relu(h2 @ W1 + b1)
    dim3 gff(FF2 / 128, NR / 128);
    sgemm_kernel<1><<<gff, 256>>>(h2, W1, ff, b1, nullptr, NR, FF2, CC);

    // out = x1 + ff @ W2 + b2
    sgemm_kernel<2><<<g512, 256>>>(ff, W2, out, b2, x1, NR, CC, FF2);
}

// round 2
// speedup vs baseline: 5.7560x; 5.7560x over previous
#include <cuda_runtime.h>
#include <math.h>
#include <stdint.h>

// Problem constants
#define BB  2
#define TT  4096
#define CC  512
#define HH  8
#define DD  64
#define FF2 2048
#define NR  (BB*TT)          // 8192 rows

// ---------------------------------------------------------------------------
// Scratch
// ---------------------------------------------------------------------------
__device__ float g_scratch[(size_t)NR*CC*7 + (size_t)NR*FF2];

// ---------------------------------------------------------------------------
// tf32 helpers
// ---------------------------------------------------------------------------
__device__ __forceinline__ float to_tf32(float x) {
    uint32_t u;
    asm("cvt.rna.tf32.f32 %0, %1;" : "=r"(u) : "f"(x));
    return __uint_as_float(u);
}

__device__ __forceinline__ void mma_tf32(float c[4],
                                         float a0, float a1, float a2, float a3,
                                         float b0, float b1) {
    asm volatile(
        "mma.sync.aligned.m16n8k8.row.col.f32.tf32.tf32.f32 "
        "{%0,%1,%2,%3},{%4,%5,%6,%7},{%8,%9},{%0,%1,%2,%3};\n"
        : "+f"(c[0]), "+f"(c[1]), "+f"(c[2]), "+f"(c[3])
        : "r"(__float_as_uint(a0)), "r"(__float_as_uint(a1)),
          "r"(__float_as_uint(a2)), "r"(__float_as_uint(a3)),
          "r"(__float_as_uint(b0)), "r"(__float_as_uint(b1)));
}

// ---------------------------------------------------------------------------
// LayerNorm: one block per row, 128 threads, 4 elems/thread
// ---------------------------------------------------------------------------
__global__ void ln_kernel(const float* __restrict__ x, const float* __restrict__ g,
                          const float* __restrict__ b, float* __restrict__ y) {
    __shared__ float sbuf[4];
    int row = blockIdx.x;
    const float* xr = x + (size_t)row * CC;
    int t = threadIdx.x;
    float v[4];
    float s = 0.f;
#pragma unroll
    for (int i = 0; i < 4; i++) { v[i] = xr[t + i * 128]; s += v[i]; }
#pragma unroll
    for (int o = 16; o; o >>= 1) s += __shfl_xor_sync(0xffffffffu, s, o);
    if ((t & 31) == 0) sbuf[t >> 5] = s;
    __syncthreads();
    float mu = (sbuf[0] + sbuf[1] + sbuf[2] + sbuf[3]) * (1.f / CC);
    __syncthreads();
    float ss = 0.f;
#pragma unroll
    for (int i = 0; i < 4; i++) { float d = v[i] - mu; ss += d * d; }
#pragma unroll
    for (int o = 16; o; o >>= 1) ss += __shfl_xor_sync(0xffffffffu, ss, o);
    if ((t & 31) == 0) sbuf[t >> 5] = ss;
    __syncthreads();
    float inv = rsqrtf((sbuf[0] + sbuf[1] + sbuf[2] + sbuf[3]) * (1.f / CC) + 1e-5f);
    float* yr = y + (size_t)row * CC;
#pragma unroll
    for (int i = 0; i < 4; i++) {
        int c = t + i * 128;
        yr[c] = (v[i] - mu) * inv * g[c] + b[c];
    }
}

// ---------------------------------------------------------------------------
// Tensor-core GEMM (tf32 mma.sync): C = A[M,K] @ B[K,N] + epilogue
//   EPI=0: none; EPI=1: relu(acc+bias); EPI=2: acc+bias+res
// Block tile 128x128, BK=32, 8 warps (2 M x 4 N), warp tile 64x32.
// Requires M%128==0, N%128==0, K%32==0.
// ---------------------------------------------------------------------------
#define ASTRIDE 36
#define BSTRIDE 136

template <int EPI>
__global__ void __launch_bounds__(256) tgemm_kernel(
    const float* __restrict__ A, const float* __restrict__ B,
    float* __restrict__ Cout, const float* __restrict__ bias,
    const float* __restrict__ res, int M, int N, int K) {
    __shared__ float As[128 * ASTRIDE];
    __shared__ float Bs[32 * BSTRIDE];

    int tid  = threadIdx.x;
    int warp = tid >> 5;
    int lane = tid & 31;
    int g    = lane >> 2;     // group 0..7
    int tg   = lane & 3;      // thread-in-group 0..3
    int warpM = warp & 1;     // 0..1
    int warpN = warp >> 1;    // 0..3

    int blockRow = blockIdx.y * 128;
    int blockCol = blockIdx.x * 128;

    float acc[4][4][4];
#pragma unroll
    for (int mt = 0; mt < 4; mt++)
#pragma unroll
        for (int nt = 0; nt < 4; nt++)
#pragma unroll
            for (int r = 0; r < 4; r++) acc[mt][nt][r] = 0.f;

    // global load indexing
    int aRow = tid >> 3;            // 0..31 (x4 passes -> 128 rows)
    int aC4  = (tid & 7) * 4;       // 0..28
    int bK   = tid >> 5;            // 0..7  (x4 passes -> 32 k-rows)
    int bN4  = (tid & 31) * 4;      // 0..124

    for (int k0 = 0; k0 < K; k0 += 32) {
        // stage A (128 x 32) with tf32 conversion
#pragma unroll
        for (int p = 0; p < 4; p++) {
            int r = aRow + p * 32;
            float4 a4 = *(const float4*)(A + (size_t)(blockRow + r) * K + k0 + aC4);
            a4.x = to_tf32(a4.x); a4.y = to_tf32(a4.y);
            a4.z = to_tf32(a4.z); a4.w = to_tf32(a4.w);
            *(float4*)&As[r * ASTRIDE + aC4] = a4;
        }
        // stage B (32 x 128) with tf32 conversion
#pragma unroll
        for (int p = 0; p < 4; p++) {
            int kr = bK + p * 8;
            float4 b4 = *(const float4*)(B + (size_t)(k0 + kr) * N + blockCol + bN4);
            b4.x = to_tf32(b4.x); b4.y = to_tf32(b4.y);
            b4.z = to_tf32(b4.z); b4.w = to_tf32(b4.w);
            *(float4*)&Bs[kr * BSTRIDE + bN4] = b4;
        }
        __syncthreads();

#pragma unroll
        for (int ks = 0; ks < 4; ks++) {
            int kk = ks * 8;
            float af[4][4];
#pragma unroll
            for (int mt = 0; mt < 4; mt++) {
                int r = warpM * 64 + mt * 16 + g;
                af[mt][0] = As[r * ASTRIDE + kk + tg];
                af[mt][1] = As[(r + 8) * ASTRIDE + kk + tg];
                af[mt][2] = As[r * ASTRIDE + kk + tg + 4];
                af[mt][3] = As[(r + 8) * ASTRIDE + kk + tg + 4];
            }
            float bf[4][2];
#pragma unroll
            for (int nt = 0; nt < 4; nt++) {
                int c = warpN * 32 + nt * 8 + g;
                bf[nt][0] = Bs[(kk + tg) * BSTRIDE + c];
                bf[nt][1] = Bs[(kk + tg + 4) * BSTRIDE + c];
            }
#pragma unroll
            for (int mt = 0; mt < 4; mt++)
#pragma unroll
                for (int nt = 0; nt < 4; nt++)
                    mma_tf32(acc[mt][nt], af[mt][0], af[mt][1], af[mt][2], af[mt][3],
                             bf[nt][0], bf[nt][1]);
        }
        __syncthreads();
    }

    // epilogue
#pragma unroll
    for (int mt = 0; mt < 4; mt++) {
#pragma unroll
        for (int nt = 0; nt < 4; nt++) {
            int row0 = blockRow + warpM * 64 + mt * 16 + g;
            int col  = blockCol + warpN * 32 + nt * 8 + 2 * tg;
#pragma unroll
            for (int h = 0; h < 2; h++) {
                int row = row0 + h * 8;
                float v0 = acc[mt][nt][2 * h];
                float v1 = acc[mt][nt][2 * h + 1];
                size_t off = (size_t)row * N + col;
                if (EPI == 1) {
                    v0 = fmaxf(v0 + bias[col], 0.f);
                    v1 = fmaxf(v1 + bias[col + 1], 0.f);
                } else if (EPI == 2) {
                    float2 rr = *(const float2*)(res + off);
                    v0 = v0 + bias[col] + rr.x;
                    v1 = v1 + bias[col + 1] + rr.y;
                }
                *(float2*)(Cout + off) = make_float2(v0, v1);
            }
        }
    }
}

// ---------------------------------------------------------------------------
// Flash attention (causal) with tf32 mma.sync.
// grid = (T/64, H, B), block = 128 (4 warps, 16 Q rows each).
// Q in register A-fragments; K/V tf32 in smem; P via warp-private smem slab.
// ---------------------------------------------------------------------------
#define KSTR 68   // Ks row stride (floats)
#define VSTR 72   // Vs row stride
#define PSTR 68   // P slab row stride
#define FLASH_FLOATS (64*KSTR + 64*VSTR + 64*PSTR)
#define FLASH_SMEM   (FLASH_FLOATS * 4)

__global__ void __launch_bounds__(128) flash_kernel(
    const float* __restrict__ q, const float* __restrict__ k,
    const float* __restrict__ v, float* __restrict__ o) {
    extern __shared__ float sm[];
    float* Ks = sm;
    float* Vs = Ks + 64 * KSTR;
    float* Pq = Vs + 64 * VSTR;   // Q staging, then per-warp P slabs

    int t    = threadIdx.x;
    int warp = t >> 5;
    int lane = t & 31;
    int g    = lane >> 2;
    int tg   = lane & 3;

    int qb = blockIdx.x;
    int hh = blockIdx.y;
    int bb = blockIdx.z;
    size_t hbase = ((size_t)bb * TT) * CC + (size_t)hh * DD;
    int qbase = qb * 64;
    const float scale = 0.04419417382415922f;  // 512^-0.5

    // stage Q (scaled, tf32) into Pq region
#pragma unroll
    for (int i = 0; i < 8; i++) {
        int idx = t + i * 128;
        int row = idx >> 4, c4 = (idx & 15) * 4;
        float4 val = *(const float4*)(q + hbase + (size_t)(qbase + row) * CC + c4);
        val.x = to_tf32(val.x * scale); val.y = to_tf32(val.y * scale);
        val.z = to_tf32(val.z * scale); val.w = to_tf32(val.w * scale);
        *(float4*)&Pq[row * PSTR + c4] = val;
    }
    __syncthreads();

    // Q A-fragments: warp rows warp*16 + g (+8), k-steps 0..7
    float qa[8][4];
#pragma unroll
    for (int ks = 0; ks < 8; ks++) {
        int r = warp * 16 + g;
        qa[ks][0] = Pq[r * PSTR + ks * 8 + tg];
        qa[ks][1] = Pq[(r + 8) * PSTR + ks * 8 + tg];
        qa[ks][2] = Pq[r * PSTR + ks * 8 + tg + 4];
        qa[ks][3] = Pq[(r + 8) * PSTR + ks * 8 + tg + 4];
    }

    float* Pw = Pq + warp * 16 * PSTR;  // warp-private P slab [16][PSTR]

    float m[2] = {-1e30f, -1e30f};
    float l[2] = {0.f, 0.f};
    float oacc[8][4];
#pragma unroll
    for (int nt = 0; nt < 8; nt++)
#pragma unroll
        for (int r = 0; r < 4; r++) oacc[nt][r] = 0.f;

    for (int kb = 0; kb <= qb; kb++) {
        int kbase = kb * 64;
        __syncthreads();   // protect Ks/Vs (+ Pq on first iter) reuse
#pragma unroll
        for (int i = 0; i < 8; i++) {
            int idx = t + i * 128;
            int row = idx >> 4, c4 = (idx & 15) * 4;
            float4 kv = *(const float4*)(k + hbase + (size_t)(kbase + row) * CC + c4);
            kv.x = to_tf32(kv.x); kv.y = to_tf32(kv.y);
            kv.z = to_tf32(kv.z); kv.w = to_tf32(kv.w);
            *(float4*)&Ks[row * KSTR + c4] = kv;
            float4 vv = *(const float4*)(v + hbase + (size_t)(kbase + row) * CC + c4);
            vv.x = to_tf32(vv.x); vv.y = to_tf32(vv.y);
            vv.z = to_tf32(vv.z); vv.w = to_tf32(vv.w);
            *(float4*)&Vs[row * VSTR + c4] = vv;
        }
        __syncthreads();

        // S = Q @ K^T : 8 n-tiles x 8 k-steps
        float s[8][4];
#pragma unroll
        for (int nt = 0; nt < 8; nt++)
#pragma unroll
            for (int r = 0; r < 4; r++) s[nt][r] = 0.f;
#pragma unroll
        for (int ks = 0; ks < 8; ks++) {
            int kk = ks * 8;
#pragma unroll
            for (int nt = 0; nt < 8; nt++) {
                int kvrow = nt * 8 + g;
                float b0 = Ks[kvrow * KSTR + kk + tg];
                float b1 = Ks[kvrow * KSTR + kk + tg + 4];
                mma_tf32(s[nt], qa[ks][0], qa[ks][1], qa[ks][2], qa[ks][3], b0, b1);
            }
        }

        // causal mask on diagonal tile
        if (kb == qb) {
#pragma unroll
            for (int nt = 0; nt < 8; nt++) {
#pragma unroll
                for (int r = 0; r < 4; r++) {
                    int row = warp * 16 + g + (r >= 2 ? 8 : 0);
                    int col = nt * 8 + 2 * tg + (r & 1);
                    if (col > row) s[nt][r] = -1e30f;
                }
            }
        }

        // online softmax (rows: half=0 -> g, half=1 -> g+8)
#pragma unroll
        for (int h = 0; h < 2; h++) {
            float mt = -1e30f;
#pragma unroll
            for (int nt = 0; nt < 8; nt++) {
                mt = fmaxf(mt, s[nt][2 * h]);
                mt = fmaxf(mt, s[nt][2 * h + 1]);
            }
            mt = fmaxf(mt, __shfl_xor_sync(0xffffffffu, mt, 1));
            mt = fmaxf(mt, __shfl_xor_sync(0xffffffffu, mt, 2));
            float mnew = fmaxf(m[h], mt);
            float corr = __expf(m[h] - mnew);
            float sum = 0.f;
#pragma unroll
            for (int nt = 0; nt < 8; nt++) {
                float p0 = __expf(s[nt][2 * h] - mnew);
                float p1 = __expf(s[nt][2 * h + 1] - mnew);
                s[nt][2 * h] = p0; s[nt][2 * h + 1] = p1;
                sum += p0 + p1;
            }
            sum += __shfl_xor_sync(0xffffffffu, sum, 1);
            sum += __shfl_xor_sync(0xffffffffu, sum, 2);
            l[h] = l[h] * corr + sum;
            m[h] = mnew;
#pragma unroll
            for (int nt = 0; nt < 8; nt++) {
                oacc[nt][2 * h]     *= corr;
                oacc[nt][2 * h + 1] *= corr;
            }
        }

        // P -> warp-private smem (tf32), C-frag layout
#pragma unroll
        for (int nt = 0; nt < 8; nt++) {
            int c = nt * 8 + 2 * tg;
            *(float2*)&Pw[g * PSTR + c] =
                make_float2(to_tf32(s[nt][0]), to_tf32(s[nt][1]));
            *(float2*)&Pw[(g + 8) * PSTR + c] =
                make_float2(to_tf32(s[nt][2]), to_tf32(s[nt][3]));
        }
        __syncwarp();

        // O += P @ V
#pragma unroll
        for (int ks = 0; ks < 8; ks++) {
            int kk = ks * 8;
            float a0 = Pw[g * PSTR + kk + tg];
            float a1 = Pw[(g + 8) * PSTR + kk + tg];
            float a2 = Pw[g * PSTR + kk + tg + 4];
            float a3 = Pw[(g + 8) * PSTR + kk + tg + 4];
#pragma unroll
            for (int nt = 0; nt < 8; nt++) {
                float b0 = Vs[(kk + tg) * VSTR + nt * 8 + g];
                float b1 = Vs[(kk + tg + 4) * VSTR + nt * 8 + g];
                mma_tf32(oacc[nt], a0, a1, a2, a3, b0, b1);
            }
        }
        __syncwarp();
    }

    // epilogue: normalize, write
#pragma unroll
    for (int h = 0; h < 2; h++) {
        float inv = 1.f / l[h];
        int row = qbase + warp * 16 + g + h * 8;
#pragma unroll
        for (int nt = 0; nt < 8; nt++) {
            int col = nt * 8 + 2 * tg;
            size_t off = hbase + (size_t)row * CC + col;
            *(float2*)(o + off) =
                make_float2(oacc[nt][2 * h] * inv, oacc[nt][2 * h + 1] * inv);
        }
    }
}

// ---------------------------------------------------------------------------
// Launch
// ---------------------------------------------------------------------------
extern "C" void kernel_launch(void* const* d_in, const int* in_sizes, int n_in,
                              void* d_out, int out_size) {
    const float* x   = (const float*)d_in[0];
    const float* Wq  = (const float*)d_in[1];
    const float* Wk  = (const float*)d_in[2];
    const float* Wv  = (const float*)d_in[3];
    const float* Wo  = (const float*)d_in[4];
    const float* bo  = (const float*)d_in[5];
    const float* W1  = (const float*)d_in[6];
    const float* b1  = (const float*)d_in[7];
    const float* W2  = (const float*)d_in[8];
    const float* b2  = (const float*)d_in[9];
    const float* g1  = (const float*)d_in[10];
    const float* be1 = (const float*)d_in[11];
    const float* g2  = (const float*)d_in[12];
    const float* be2 = (const float*)d_in[13];
    float* out = (float*)d_out;

    float* base = nullptr;
    cudaGetSymbolAddress((void**)&base, g_scratch);
    const size_t SZ = (size_t)NR * CC;
    float* h    = base;
    float* q    = base + SZ * 1;
    float* k    = base + SZ * 2;
    float* v    = base + SZ * 3;
    float* attn = base + SZ * 4;
    float* x1   = base + SZ * 5;
    float* h2   = base + SZ * 6;
    float* ff   = base + SZ * 7;

    cudaFuncSetAttribute(flash_kernel,
                         cudaFuncAttributeMaxDynamicSharedMemorySize, FLASH_SMEM);

    // ln1
    ln_kernel<<<NR, 128>>>(x, g1, be1, h);

    // q,k,v = h @ W{q,k,v}
    dim3 g512(CC / 128, NR / 128);
    tgemm_kernel<0><<<g512, 256>>>(h, Wq, q, nullptr, nullptr, NR, CC, CC);
    tgemm_kernel<0><<<g512, 256>>>(h, Wk, k, nullptr, nullptr, NR, CC, CC);
    tgemm_kernel<0><<<g512, 256>>>(h, Wv, v, nullptr, nullptr, NR, CC, CC);

    // attention
    flash_kernel<<<dim3(TT / 64, HH, BB), 128, FLASH_SMEM>>>(q, k, v, attn);

    // x1 = x + attn @ Wo + bo
    tgemm_kernel<2><<<g512, 256>>>(attn, Wo, x1, bo, x, NR, CC, CC);

    // ln2
    ln_kernel<<<NR, 128>>>(x1, g2, be2, h2);

    // ff = relu(h2 @ W1 + b1)
    dim3 gff(FF2 / 128, NR / 128);
    tgemm_kernel<1><<<gff, 256>>>(h2, W1, ff, b1, nullptr, NR, FF2, CC);

    // out = x1 + ff @ W2 + b2
    tgemm_kernel<2><<<g512, 256>>>(ff, W2, out, b2, x1, NR, CC, FF2);
}

// round 5
// speedup vs baseline: 11.8807x; 2.0640x over previous
#include <cuda_runtime.h>
#include <cuda_fp16.h>
#include <math.h>
#include <stdint.h>

// Problem constants
#define BB  2
#define TT  4096
#define CC  512
#define HH  8
#define DD  64
#define FF2 2048
#define NR  (BB*TT)          // 8192 rows
#define QKVC 1536            // fused qkv row width (halfs)

// ---------------------------------------------------------------------------
// Scratch (bytes, 16B aligned). Layout below in kernel_launch.
// ---------------------------------------------------------------------------
__device__ float4 g_scratch[6684672];   // 106,954,752 bytes

// ---------------------------------------------------------------------------
// PTX helpers
// ---------------------------------------------------------------------------
__device__ __forceinline__ uint32_t smem_u32(const void* p) {
    uint32_t a;
    asm("{ .reg .u64 t; cvta.to.shared.u64 t, %1; cvt.u32.u64 %0, t; }"
        : "=r"(a) : "l"(p));
    return a;
}

__device__ __forceinline__ uint32_t h2_as_u32(__half2 h) {
    union { __half2 h; uint32_t u; } cvt;
    cvt.h = h;
    return cvt.u;
}

__device__ __forceinline__ void ldsm_x4(uint32_t& r0, uint32_t& r1,
                                        uint32_t& r2, uint32_t& r3, uint32_t addr) {
    asm volatile("ldmatrix.sync.aligned.m8n8.x4.shared.b16 {%0,%1,%2,%3}, [%4];"
                 : "=r"(r0), "=r"(r1), "=r"(r2), "=r"(r3) : "r"(addr));
}
__device__ __forceinline__ void ldsm_x4t(uint32_t& r0, uint32_t& r1,
                                         uint32_t& r2, uint32_t& r3, uint32_t addr) {
    asm volatile("ldmatrix.sync.aligned.m8n8.x4.trans.shared.b16 {%0,%1,%2,%3}, [%4];"
                 : "=r"(r0), "=r"(r1), "=r"(r2), "=r"(r3) : "r"(addr));
}

__device__ __forceinline__ void mma_f16(float c[4], uint32_t a0, uint32_t a1,
                                        uint32_t a2, uint32_t a3,
                                        uint32_t b0, uint32_t b1) {
    asm volatile(
        "mma.sync.aligned.m16n8k16.row.col.f32.f16.f16.f32 "
        "{%0,%1,%2,%3},{%4,%5,%6,%7},{%8,%9},{%0,%1,%2,%3};\n"
        : "+f"(c[0]), "+f"(c[1]), "+f"(c[2]), "+f"(c[3])
        : "r"(a0), "r"(a1), "r"(a2), "r"(a3), "r"(b0), "r"(b1));
}

#define CP_ASYNC16(dst, src) \
    asm volatile("cp.async.cg.shared.global [%0], [%1], 16;" :: "r"(dst), "l"(src))
#define CP_COMMIT() asm volatile("cp.async.commit_group;" ::: "memory")
#define CP_WAIT(n)  asm volatile("cp.async.wait_group %0;" :: "n"(n) : "memory")

// ---------------------------------------------------------------------------
// Weight transpose + fp32->fp16: in[R][C] -> out[C][R]
// ---------------------------------------------------------------------------
__global__ void convert_w_kernel(const float* __restrict__ in, __half* __restrict__ out,
                                 int R, int C) {
    __shared__ float tile[32][33];
    int bx = blockIdx.x * 32, by = blockIdx.y * 32;
    int x = threadIdx.x, y = threadIdx.y;
#pragma unroll
    for (int j = 0; j < 32; j += 8)
        tile[y + j][x] = in[(size_t)(by + y + j) * C + bx + x];
    __syncthreads();
#pragma unroll
    for (int j = 0; j < 32; j += 8)
        out[(size_t)(bx + y + j) * R + by + x] = __float2half(tile[x][y + j]);
}

// ---------------------------------------------------------------------------
// LayerNorm: fp32 in -> fp16 out
// ---------------------------------------------------------------------------
__global__ void ln_kernel(const float* __restrict__ x, const float* __restrict__ g,
                          const float* __restrict__ b, __half* __restrict__ y) {
    __shared__ float sbuf[4];
    int row = blockIdx.x;
    const float* xr = x + (size_t)row * CC;
    int t = threadIdx.x;
    float v[4];
    float s = 0.f;
#pragma unroll
    for (int i = 0; i < 4; i++) { v[i] = xr[t + i * 128]; s += v[i]; }
#pragma unroll
    for (int o = 16; o; o >>= 1) s += __shfl_xor_sync(0xffffffffu, s, o);
    if ((t & 31) == 0) sbuf[t >> 5] = s;
    __syncthreads();
    float mu = (sbuf[0] + sbuf[1] + sbuf[2] + sbuf[3]) * (1.f / CC);
    __syncthreads();
    float ss = 0.f;
#pragma unroll
    for (int i = 0; i < 4; i++) { float d = v[i] - mu; ss += d * d; }
#pragma unroll
    for (int o = 16; o; o >>= 1) ss += __shfl_xor_sync(0xffffffffu, ss, o);
    if ((t & 31) == 0) sbuf[t >> 5] = ss;
    __syncthreads();
    float inv = rsqrtf((sbuf[0] + sbuf[1] + sbuf[2] + sbuf[3]) * (1.f / CC) + 1e-5f);
    __half* yr = y + (size_t)row * CC;
#pragma unroll
    for (int i = 0; i < 4; i++) {
        int c = t + i * 128;
        yr[c] = __float2half((v[i] - mu) * inv * g[c] + b[c]);
    }
}

// ---------------------------------------------------------------------------
// fp16 tensor-core GEMM: C = A[M,K] @ Bt[N,K]^T (+epilogue)
//   EPI=0: write fp16          EPI=1: relu(+bias) fp16
//   EPI=2: +bias +res(fp32) -> fp32
// 128x128 tile, BK=64 halfs (128B rows, XOR swizzle), 3-stage cp.async,
// 8 warps (2M x 4N), warp tile 64x32, m16n8k16.
// ---------------------------------------------------------------------------
#define HG_STAGE 32768
#define HG_SMEM  (3 * HG_STAGE)

template <int EPI>
__global__ void __launch_bounds__(256) hgemm_kernel(
    const __half* __restrict__ A, const __half* __restrict__ Bt,
    void* __restrict__ Cout_, const float* __restrict__ bias,
    const float* __restrict__ res, int M, int N, int K) {
    extern __shared__ char sm[];
    uint32_t sbase = smem_u32(sm);
    int tid = threadIdx.x, warp = tid >> 5, lane = tid & 31;
    int warpM = warp & 1, warpN = warp >> 1;
    int blockRow = blockIdx.y * 128, blockCol = blockIdx.x * 128;

    float acc[4][4][4];
#pragma unroll
    for (int mt = 0; mt < 4; mt++)
#pragma unroll
        for (int nt = 0; nt < 4; nt++)
#pragma unroll
            for (int r = 0; r < 4; r++) acc[mt][nt][r] = 0.f;

    // per-thread cp.async chunk coords (4 chunks per operand per stage)
    int crow[4], cc16[4];
#pragma unroll
    for (int p = 0; p < 4; p++) {
        int idx = tid + p * 256;
        crow[p] = idx >> 3;
        cc16[p] = idx & 7;
    }

    int nchunks = K >> 6;  // BK=64 halfs

#define LOAD_STAGE(cidx) do {                                                   \
    int _st = (cidx) % 3;                                                       \
    int _k0 = (cidx) << 6;                                                      \
    uint32_t _ab = sbase + _st * HG_STAGE;                                      \
    uint32_t _bb = _ab + 16384;                                                 \
    _Pragma("unroll")                                                           \
    for (int p = 0; p < 4; p++) {                                               \
        int _r = crow[p], _c = cc16[p];                                         \
        uint32_t _sw = (uint32_t)((_c ^ (_r & 7)) * 16);                        \
        CP_ASYNC16(_ab + _r * 128 + _sw,                                        \
                   A + (size_t)(blockRow + _r) * K + _k0 + _c * 8);             \
        CP_ASYNC16(_bb + _r * 128 + _sw,                                        \
                   Bt + (size_t)(blockCol + _r) * K + _k0 + _c * 8);            \
    }                                                                           \
    CP_COMMIT();                                                                \
} while (0)

    LOAD_STAGE(0);
    LOAD_STAGE(1);

    for (int c = 0; c < nchunks; c++) {
        if (c + 2 < nchunks) { LOAD_STAGE(c + 2); CP_WAIT(2); }
        else if (c + 1 < nchunks) { CP_WAIT(1); }
        else { CP_WAIT(0); }
        __syncthreads();

        uint32_t as = sbase + (c % 3) * HG_STAGE;
        uint32_t bs = as + 16384;
#pragma unroll
        for (int kstep = 0; kstep < 4; kstep++) {
            uint32_t a[4][4];
#pragma unroll
            for (int mt = 0; mt < 4; mt++) {
                int row = warpM * 64 + mt * 16 + (lane & 15);
                uint32_t chunk = (uint32_t)((kstep * 2 + (lane >> 4)) ^ (row & 7));
                ldsm_x4(a[mt][0], a[mt][1], a[mt][2], a[mt][3],
                        as + row * 128 + chunk * 16);
            }
            uint32_t b[4][2];
#pragma unroll
            for (int ntp = 0; ntp < 2; ntp++) {
                int row = warpN * 32 + ntp * 16 + (lane & 15);
                uint32_t chunk = (uint32_t)((kstep * 2 + (lane >> 4)) ^ (row & 7));
                uint32_t r0, r1, r2, r3;
                ldsm_x4(r0, r1, r2, r3, bs + row * 128 + chunk * 16);
                b[2 * ntp][0] = r0; b[2 * ntp][1] = r2;
                b[2 * ntp + 1][0] = r1; b[2 * ntp + 1][1] = r3;
            }
#pragma unroll
            for (int mt = 0; mt < 4; mt++)
#pragma unroll
                for (int nt = 0; nt < 4; nt++)
                    mma_f16(acc[mt][nt], a[mt][0], a[mt][1], a[mt][2], a[mt][3],
                            b[nt][0], b[nt][1]);
        }
        __syncthreads();
    }
#undef LOAD_STAGE

    // epilogue
    int g = lane >> 2, tg = lane & 3;
#pragma unroll
    for (int mt = 0; mt < 4; mt++) {
#pragma unroll
        for (int nt = 0; nt < 4; nt++) {
            int row0 = blockRow + warpM * 64 + mt * 16 + g;
            int col  = blockCol + warpN * 32 + nt * 8 + 2 * tg;
#pragma unroll
            for (int hh = 0; hh < 2; hh++) {
                int row = row0 + hh * 8;
                float v0 = acc[mt][nt][2 * hh];
                float v1 = acc[mt][nt][2 * hh + 1];
                size_t off = (size_t)row * N + col;
                if (EPI == 0) {
                    *(__half2*)((__half*)Cout_ + off) = __floats2half2_rn(v0, v1);
                } else if (EPI == 1) {
                    v0 = fmaxf(v0 + bias[col], 0.f);
                    v1 = fmaxf(v1 + bias[col + 1], 0.f);
                    *(__half2*)((__half*)Cout_ + off) = __floats2half2_rn(v0, v1);
                } else {
                    float* Cf = (float*)Cout_;
                    float2 rr = *(const float2*)(res + off);
                    *(float2*)(Cf + off) =
                        make_float2(v0 + bias[col] + rr.x, v1 + bias[col + 1] + rr.y);
                }
            }
        }
    }
}

// ---------------------------------------------------------------------------
// Flash attention (causal), fp16 mma m16n8k16.
// grid = (T/64, H, B), 128 threads (4 warps, 16 q-rows each).
// Q frags in regs; K non-trans ldmatrix; V ldmatrix.x4.trans;
// P reused from S C-fragment (no smem round trip).
// Tiles 64x64 fp16, row stride 72 halfs (conflict-free, no swizzle).
// ---------------------------------------------------------------------------
#define FTS 72   // halfs per row

__global__ void __launch_bounds__(128) flash_kernel(
    const __half* __restrict__ qkv, __half* __restrict__ o) {
    __shared__ __half Qs[64 * FTS];
    __shared__ __half Ks[64 * FTS];
    __shared__ __half Vs[64 * FTS];
    uint32_t qs_b = smem_u32(Qs), ks_b = smem_u32(Ks), vs_b = smem_u32(Vs);

    int t = threadIdx.x, warp = t >> 5, lane = t & 31;
    int g = lane >> 2, tg = lane & 3;
    int qb = blockIdx.x, hh = blockIdx.y, bb = blockIdx.z;
    size_t hbase = ((size_t)bb * TT) * QKVC + (size_t)hh * DD;  // q offset (halfs)
    size_t obase = ((size_t)bb * TT) * CC + (size_t)hh * DD;
    int qbase = qb * 64;
    const float scale = 0.04419417382415922f;  // 512^-0.5

    const __half* qp = qkv;
    const __half* kp = qkv + CC;
    const __half* vp = qkv + 2 * CC;

    // load Q tile
#pragma unroll
    for (int i = 0; i < 4; i++) {
        int idx = t + i * 128;
        int row = idx >> 3, c = idx & 7;
        *(uint4*)&Qs[row * FTS + c * 8] =
            *(const uint4*)(qp + hbase + (size_t)(qbase + row) * QKVC + c * 8);
    }
    __syncthreads();

    // hoist Q fragments
    uint32_t qa[4][4];
#pragma unroll
    for (int ks = 0; ks < 4; ks++) {
        int row = warp * 16 + (lane & 15);
        int chunk = ks * 2 + (lane >> 4);
        ldsm_x4(qa[ks][0], qa[ks][1], qa[ks][2], qa[ks][3],
                qs_b + row * (FTS * 2) + chunk * 16);
    }

    float m[2] = {-1e30f, -1e30f};
    float l[2] = {0.f, 0.f};
    float oacc[8][4];
#pragma unroll
    for (int nt = 0; nt < 8; nt++)
#pragma unroll
        for (int r = 0; r < 4; r++) oacc[nt][r] = 0.f;

    for (int kb = 0; kb <= qb; kb++) {
        int kbase = kb * 64;
        __syncthreads();
#pragma unroll
        for (int i = 0; i < 4; i++) {
            int idx = t + i * 128;
            int row = idx >> 3, c = idx & 7;
            size_t src = hbase + (size_t)(kbase + row) * QKVC + c * 8;
            *(uint4*)&Ks[row * FTS + c * 8] = *(const uint4*)(kp + src);
            *(uint4*)&Vs[row * FTS + c * 8] = *(const uint4*)(vp + src);
        }
        __syncthreads();

        // S = Q @ K^T
        float s[8][4];
#pragma unroll
        for (int nt = 0; nt < 8; nt++)
#pragma unroll
            for (int r = 0; r < 4; r++) s[nt][r] = 0.f;
#pragma unroll
        for (int ks = 0; ks < 4; ks++) {
#pragma unroll
            for (int ntp = 0; ntp < 4; ntp++) {
                int row = ntp * 16 + (lane & 15);
                int chunk = ks * 2 + (lane >> 4);
                uint32_t r0, r1, r2, r3;
                ldsm_x4(r0, r1, r2, r3, ks_b + row * (FTS * 2) + chunk * 16);
                mma_f16(s[2 * ntp],     qa[ks][0], qa[ks][1], qa[ks][2], qa[ks][3], r0, r2);
                mma_f16(s[2 * ntp + 1], qa[ks][0], qa[ks][1], qa[ks][2], qa[ks][3], r1, r3);
            }
        }

        // scale
#pragma unroll
        for (int nt = 0; nt < 8; nt++)
#pragma unroll
            for (int r = 0; r < 4; r++) s[nt][r] *= scale;

        // causal mask on diagonal tile
        if (kb == qb) {
#pragma unroll
            for (int nt = 0; nt < 8; nt++) {
#pragma unroll
                for (int r = 0; r < 4; r++) {
                    int row = warp * 16 + g + (r >= 2 ? 8 : 0);
                    int col = nt * 8 + 2 * tg + (r & 1);
                    if (col > row) s[nt][r] = -1e30f;
                }
            }
        }

        // online softmax (h=0 -> row g, h=1 -> row g+8)
#pragma unroll
        for (int h = 0; h < 2; h++) {
            float mt = -1e30f;
#pragma unroll
            for (int nt = 0; nt < 8; nt++) {
                mt = fmaxf(mt, s[nt][2 * h]);
                mt = fmaxf(mt, s[nt][2 * h + 1]);
            }
            mt = fmaxf(mt, __shfl_xor_sync(0xffffffffu, mt, 1));
            mt = fmaxf(mt, __shfl_xor_sync(0xffffffffu, mt, 2));
            float mnew = fmaxf(m[h], mt);
            float corr = __expf(m[h] - mnew);
            float sum = 0.f;
#pragma unroll
            for (int nt = 0; nt < 8; nt++) {
                float p0 = __expf(s[nt][2 * h] - mnew);
                float p1 = __expf(s[nt][2 * h + 1] - mnew);
                s[nt][2 * h] = p0; s[nt][2 * h + 1] = p1;
                sum += p0 + p1;
            }
            sum += __shfl_xor_sync(0xffffffffu, sum, 1);
            sum += __shfl_xor_sync(0xffffffffu, sum, 2);
            l[h] = l[h] * corr + sum;
            m[h] = mnew;
#pragma unroll
            for (int nt = 0; nt < 8; nt++) {
                oacc[nt][2 * h]     *= corr;
                oacc[nt][2 * h + 1] *= corr;
            }
        }

        // O += P @ V ; P fragments straight from s
#pragma unroll
        for (int kt = 0; kt < 4; kt++) {
            uint32_t pa0 = h2_as_u32(__floats2half2_rn(s[2 * kt][0], s[2 * kt][1]));
            uint32_t pa1 = h2_as_u32(__floats2half2_rn(s[2 * kt][2], s[2 * kt][3]));
            uint32_t pa2 = h2_as_u32(__floats2half2_rn(s[2 * kt + 1][0], s[2 * kt + 1][1]));
            uint32_t pa3 = h2_as_u32(__floats2half2_rn(s[2 * kt + 1][2], s[2 * kt + 1][3]));
#pragma unroll
            for (int ntp = 0; ntp < 4; ntp++) {
                int row = kt * 16 + (lane & 15);
                int chunk = ntp * 2 + (lane >> 4);
                uint32_t r0, r1, r2, r3;
                ldsm_x4t(r0, r1, r2, r3, vs_b + row * (FTS * 2) + chunk * 16);
                mma_f16(oacc[2 * ntp],     pa0, pa1, pa2, pa3, r0, r1);
                mma_f16(oacc[2 * ntp + 1], pa0, pa1, pa2, pa3, r2, r3);
            }
        }
    }

    // epilogue
#pragma unroll
    for (int h = 0; h < 2; h++) {
        float inv = 1.f / l[h];
        int row = qbase + warp * 16 + g + h * 8;
#pragma unroll
        for (int nt = 0; nt < 8; nt++) {
            int col = nt * 8 + 2 * tg;
            size_t off = obase + (size_t)row * CC + col;
            *(__half2*)(o + off) =
                __floats2half2_rn(oacc[nt][2 * h] * inv, oacc[nt][2 * h + 1] * inv);
        }
    }
}

// ---------------------------------------------------------------------------
// Launch
// ---------------------------------------------------------------------------
extern "C" void kernel_launch(void* const* d_in, const int* in_sizes, int n_in,
                              void* d_out, int out_size) {
    const float* x   = (const float*)d_in[0];
    const float* Wq  = (const float*)d_in[1];
    const float* Wk  = (const float*)d_in[2];
    const float* Wv  = (const float*)d_in[3];
    const float* Wo  = (const float*)d_in[4];
    const float* bo  = (const float*)d_in[5];
    const float* W1  = (const float*)d_in[6];
    const float* b1  = (const float*)d_in[7];
    const float* W2  = (const float*)d_in[8];
    const float* b2  = (const float*)d_in[9];
    const float* g1  = (const float*)d_in[10];
    const float* be1 = (const float*)d_in[11];
    const float* g2  = (const float*)d_in[12];
    const float* be2 = (const float*)d_in[13];
    float* out = (float*)d_out;

    char* base = nullptr;
    cudaGetSymbolAddress((void**)&base, g_scratch);
    __half* h16   = (__half*)(base);                       //  8 MB
    __half* qkv16 = (__half*)(base + 8388608);             // 24 MB
    __half* attn16= (__half*)(base + 33554432);            //  8 MB
    float*  x1f   = (float*)(base + 41943040);             // 16 MB
    __half* h2_16 = (__half*)(base + 58720256);            //  8 MB
    __half* ff16  = (__half*)(base + 67108864);            // 32 MB
    __half* wqkvT = (__half*)(base + 100663296);           // 1.5 MB
    __half* woT   = (__half*)(base + 102236160);
    __half* w1T   = (__half*)(base + 102760448);
    __half* w2T   = (__half*)(base + 104857600);

    cudaFuncSetAttribute(hgemm_kernel<0>, cudaFuncAttributeMaxDynamicSharedMemorySize, HG_SMEM);
    cudaFuncSetAttribute(hgemm_kernel<1>, cudaFuncAttributeMaxDynamicSharedMemorySize, HG_SMEM);
    cudaFuncSetAttribute(hgemm_kernel<2>, cudaFuncAttributeMaxDynamicSharedMemorySize, HG_SMEM);

    dim3 tb(32, 8);
    convert_w_kernel<<<dim3(CC / 32, CC / 32), tb>>>(Wq, wqkvT, CC, CC);
    convert_w_kernel<<<dim3(CC / 32, CC / 32), tb>>>(Wk, wqkvT + (size_t)CC * CC, CC, CC);
    convert_w_kernel<<<dim3(CC / 32, CC / 32), tb>>>(Wv, wqkvT + (size_t)2 * CC * CC, CC, CC);
    convert_w_kernel<<<dim3(CC / 32, CC / 32), tb>>>(Wo, woT, CC, CC);
    convert_w_kernel<<<dim3(FF2 / 32, CC / 32), tb>>>(W1, w1T, CC, FF2);
    convert_w_kernel<<<dim3(CC / 32, FF2 / 32), tb>>>(W2, w2T, FF2, CC);

    // ln1: h = LN(x)
    ln_kernel<<<NR, 128>>>(x, g1, be1, h16);

    // qkv = h @ [Wq|Wk|Wv]
    hgemm_kernel<0><<<dim3(QKVC / 128, NR / 128), 256, HG_SMEM>>>(
        h16, wqkvT, qkv16, nullptr, nullptr, NR, QKVC, CC);

    // attention
    flash_kernel<<<dim3(TT / 64, HH, BB), 128>>>(qkv16, attn16);

    // x1 = x + attn @ Wo + bo   (fp32 out)
    hgemm_kernel<2><<<dim3(CC / 128, NR / 128), 256, HG_SMEM>>>(
        attn16, woT, x1f, bo, x, NR, CC, CC);

    // ln2
    ln_kernel<<<NR, 128>>>(x1f, g2, be2, h2_16);

    // ff = relu(h2 @ W1 + b1)
    hgemm_kernel<1><<<dim3(FF2 / 128, NR / 128), 256, HG_SMEM>>>(
        h2_16, w1T, ff16, b1, nullptr, NR, FF2, CC);

    // out = x1 + ff @ W2 + b2  (fp32 out)
    hgemm_kernel<2><<<dim3(CC / 128, NR / 128), 256, HG_SMEM>>>(
        ff16, w2T, out, b2, x1f, NR, CC, FF2);
}